// round 1
// baseline (speedup 1.0000x reference)
#include <cuda_runtime.h>
#include <cuda_bf16.h>

// SurfEval: NURBS-like surface evaluation.
// B=16, M=N=64, P=Q=3, OUT_U=OUT_V=256, DIM=3 (ctrl has DIM+1=4 channels, last unused).
// Faithful quirks of the reference:
//   * V is built from knot_u (knot_v is dead input) -> Nv==Nu, vspan==uspan.
//   * span = argmin over cand = (t - K[3+s] > 1e-8) ? d : 1.0, first-min tie-break.
//   * Cox-de Boor denominator written as (K1 - t) + (t - K2).

#define BSZ   16
#define MC    64
#define NC    64
#define DEG   3
#define LK    (MC + DEG + 1)   // 68 knots
#define OUTN  256

// Scratch (static device arrays: no allocation in kernel_launch).
__device__ float g_basis[BSZ * OUTN * 4];
__device__ int   g_span [BSZ * OUTN];

// ---------------------------------------------------------------------------
// Kernel A: per-batch normalized knots, span + basis per eval point.
// Grid: 16 blocks (one per batch), 256 threads (one per eval parameter).
// ---------------------------------------------------------------------------
__global__ void surfeval_basis_kernel(const float* __restrict__ knot_u)
{
    __shared__ float U[LK];
    const int b = blockIdx.x;

    if (threadIdx.x == 0) {
        // sequential cumsum + normalize (matches numpy/jax semantics closely)
        float cs[LK];
        float c = 0.f;
        #pragma unroll 1
        for (int i = 0; i < LK; i++) { c += knot_u[b * LK + i]; cs[i] = c; }
        const float c0  = cs[0];
        const float inv = 1.0f / (cs[LK - 1] - c0);
        #pragma unroll 1
        for (int i = 0; i < LK; i++) U[i] = (cs[i] - c0) * inv;
    }
    __syncthreads();

    const int i = threadIdx.x;                       // 0..255
    const float step = (1.0f - 2e-5f) / (float)(OUTN - 1);
    const float t = 1e-5f + (float)i * step;

    // find_span: argmin of cand = (d > 1e-8) ? d : 1.0 over s in [0, 62), +DEG
    float best = 1.0f;
    int bs = 0;
    #pragma unroll 1
    for (int s = 0; s < LK - 2 * DEG; s++) {
        const float d = t - U[DEG + s];
        const float cand = (d > 1e-8f) ? d : 1.0f;
        if (cand < best) { best = cand; bs = s; }    // strict < == first-min
    }
    const int span = bs + DEG;

    // Cox-de Boor (deg 3), exact expression order of the reference
    float Nb[DEG + 1];
    Nb[0] = 1.0f;
    #pragma unroll
    for (int k = 1; k <= DEG; k++) {
        float saved = 0.0f;
        #pragma unroll
        for (int r = 0; r < k; r++) {
            const float K1 = U[span + r + 1];
            const float K2 = U[span + 1 - k + r];
            const float temp = Nb[r] / ((K1 - t) + (t - K2));
            Nb[r] = saved + (K1 - t) * temp;
            saved = (t - K2) * temp;
        }
        Nb[k] = saved;
    }

    g_span[b * OUTN + i] = span;
    #pragma unroll
    for (int l = 0; l <= DEG; l++)
        g_basis[(b * OUTN + i) * 4 + l] = Nb[l];
}

// ---------------------------------------------------------------------------
// Kernel B: evaluate one (b, u) output row per block; 256 threads over v.
// SMEM-stage the 4 needed ctrl rows (4 KB) -> steady-state HBM traffic is
// essentially just the 12.6 MB output write. Output row staged in SMEM and
// written with stride-1 coalesced stores.
// ---------------------------------------------------------------------------
__global__ __launch_bounds__(256)
void surfeval_eval_kernel(const float4* __restrict__ ctrl,
                          float* __restrict__ out)
{
    __shared__ float4 rows[4][NC];       // 4 KB: ctrl[b][iu0..iu0+3][0..63]
    __shared__ float  stage[OUTN * 3];   // 3 KB: output row staging

    const int u = blockIdx.x;
    const int b = blockIdx.y;
    const int tid = threadIdx.x;

    const int span_u = g_span[b * OUTN + u];
    const int iu0 = span_u - DEG;

    // cooperative load: 4 rows x 64 float4 = 256 float4 = 1 per thread
    {
        const int l = tid >> 6;          // 0..3
        const int c = tid & 63;          // 0..63
        rows[l][c] = ctrl[((size_t)b * MC + iu0 + l) * NC + c];
    }
    __syncthreads();

    const int v = tid;
    const int iv0 = g_span[b * OUTN + v] - DEG;

    float nu[4], nv[4];
    #pragma unroll
    for (int l = 0; l < 4; l++) {
        nu[l] = g_basis[(b * OUTN + u) * 4 + l];   // uniform across block
        nv[l] = g_basis[(b * OUTN + v) * 4 + l];
    }

    float ax = 0.f, ay = 0.f, az = 0.f;
    #pragma unroll
    for (int l = 0; l < 4; l++) {
        float tx = 0.f, ty = 0.f, tz = 0.f;
        #pragma unroll
        for (int r = 0; r < 4; r++) {
            const float4 cp = rows[l][iv0 + r];
            tx = fmaf(nv[r], cp.x, tx);
            ty = fmaf(nv[r], cp.y, ty);
            tz = fmaf(nv[r], cp.z, tz);
        }
        ax = fmaf(nu[l], tx, ax);
        ay = fmaf(nu[l], ty, ay);
        az = fmaf(nu[l], tz, az);
    }

    stage[v * 3 + 0] = ax;
    stage[v * 3 + 1] = ay;
    stage[v * 3 + 2] = az;
    __syncthreads();

    // coalesced row write: 768 contiguous floats
    float* orow = out + ((size_t)(b * OUTN + u) * OUTN) * 3;
    orow[tid]           = stage[tid];
    orow[tid + OUTN]    = stage[tid + OUTN];
    orow[tid + 2*OUTN]  = stage[tid + 2*OUTN];
}

// ---------------------------------------------------------------------------
extern "C" void kernel_launch(void* const* d_in, const int* in_sizes, int n_in,
                              void* d_out, int out_size)
{
    const float4* ctrl   = (const float4*)d_in[0];   // [16,64,64,4] f32
    const float*  knot_u = (const float*)d_in[1];    // [16,68] f32
    // d_in[2] = knot_v : unused (reference builds V from knot_u)
    float* out = (float*)d_out;                      // [16,256,256,3] f32

    surfeval_basis_kernel<<<BSZ, OUTN>>>(knot_u);
    dim3 grid(OUTN, BSZ);
    surfeval_eval_kernel<<<grid, OUTN>>>(ctrl, out);
}